// round 10
// baseline (speedup 1.0000x reference)
#include <cuda_runtime.h>
#include <cstdint>

// nu_grid_sampler: out[b,c,n] = x[b,c,px,py], x:(8,128,256,256) f32,
// coords:(8,32768,2) f32, out:(8,128,32768) f32.
//
// R10 = R9 (TMA bulk stage copies, 4 x 16K-pixel stages, 3 x 64KB ring,
// lookahead 2) with:
//  (a) register accumulation: per-stage predicated LDS fill vlo[16]/vhi[16]
//      registers; ONE dense fully-coalesced store pass at the end (stores
//      issue /4, each out line written once instead of 4 partial touches);
//  (b) index computation fused into the prologue (overlaps TMA latency of
//      stages 0/1), removing the separate idx_kernel launch (~7.5us).

#define GS_B 8
#define GS_C 128
#define GS_NX 256
#define GS_NY 256
#define GS_N 32768
#define GS_PIX (GS_NX * GS_NY)            // 65536
#define GS_HALF_N (GS_N / 2)              // 16384 pairs
#define STAGE_PIX 16384                    // 64KB per stage
#define STAGE_BYTES (STAGE_PIX * 4)
#define NUM_STAGES 4
#define NUM_BUFS 3
#define K2_THREADS 1024
#define PAIRS_PER_THREAD (GS_HALF_N / K2_THREADS)  // 16

__device__ __forceinline__ unsigned int compute_idx(float cy, float cx) {
    float pxf = fminf(fmaxf(cx * (float)(GS_NX - 1), 0.0f), (float)GS_NX);
    float pyf = fminf(fmaxf(cy * (float)(GS_NY - 1), 0.0f), (float)GS_NY);
    int idx = (int)pxf * GS_NY + (int)pyf;
    return (unsigned int)min(idx, GS_PIX - 1);       // take_along_axis clamp
}

__device__ __forceinline__ uint32_t smem_u32(const void* p) {
    uint32_t a;
    asm("{ .reg .u64 t; cvta.to.shared.u64 t, %1; cvt.u32.u64 %0, t; }"
        : "=r"(a) : "l"(p));
    return a;
}

// Single-thread bulk copy of one 64KB stage with transaction-tracked mbarrier.
__device__ __forceinline__ void bulk_copy_stage(uint32_t smem_dst, const float* gsrc,
                                                uint32_t mbar) {
    asm volatile("mbarrier.arrive.expect_tx.shared.b64 _, [%0], %1;"
                 :: "r"(mbar), "r"((unsigned)STAGE_BYTES) : "memory");
    asm volatile("cp.async.bulk.shared::cta.global.mbarrier::complete_tx::bytes "
                 "[%0], [%1], %2, [%3];"
                 :: "r"(smem_dst), "l"(gsrc), "r"((unsigned)STAGE_BYTES), "r"(mbar)
                 : "memory");
}

__device__ __forceinline__ void mbar_wait(uint32_t mbar, unsigned phase) {
    asm volatile(
        "{\n\t"
        ".reg .pred P;\n\t"
        "LAB_WAIT_%=:\n\t"
        "mbarrier.try_wait.parity.acquire.cta.shared::cta.b64 P, [%0], %1, 0x989680;\n\t"
        "@P bra.uni LAB_DONE_%=;\n\t"
        "bra.uni LAB_WAIT_%=;\n\t"
        "LAB_DONE_%=:\n\t"
        "}"
        :: "r"(mbar), "r"(phase) : "memory");
}

__global__ __launch_bounds__(K2_THREADS, 1)
void gather_kernel(const float* __restrict__ x,
                   const float* __restrict__ coords,
                   float* __restrict__ out) {
    extern __shared__ float sbuf[];                  // 3 * 16384 floats = 192KB
    __shared__ __align__(8) unsigned long long mbar_store[NUM_BUFS];
    const int tid = threadIdx.x;
    const int bc  = blockIdx.x;                      // b*128 + c
    const int b   = bc >> 7;

    const float* __restrict__ plane = x + ((size_t)bc << 16);
    float* __restrict__ ob          = out + ((size_t)bc << 15);

    const uint32_t sb  = smem_u32(sbuf);
    const uint32_t mb0 = smem_u32(mbar_store);

    if (tid == 0) {
        #pragma unroll
        for (int q = 0; q < NUM_BUFS; ++q)
            asm volatile("mbarrier.init.shared.b64 [%0], 1;"
                         :: "r"(mb0 + q * 8) : "memory");
    }
    __syncthreads();   // mbarrier init visible before any TMA

    // Issue stages 0 and 1 first so coords loads below overlap the TMA latency.
    if (tid == 0) {
        bulk_copy_stage(sb + 0 * STAGE_BYTES, plane + 0 * (size_t)STAGE_PIX, mb0 + 0);
        bulk_copy_stage(sb + 1 * STAGE_BYTES, plane + 1 * (size_t)STAGE_PIX, mb0 + 8);
    }

    // Fused index computation: this thread's 16 point-pairs (coalesced float2).
    unsigned int pair[PAIRS_PER_THREAD];
    {
        const float2* __restrict__ cb =
            reinterpret_cast<const float2*>(coords) + (size_t)b * GS_N + tid;
        #pragma unroll
        for (int k = 0; k < PAIRS_PER_THREAD; ++k) {
            float2 c_lo = cb[k << 10];
            float2 c_hi = cb[(k << 10) + GS_HALF_N];
            pair[k] = compute_idx(c_lo.x, c_lo.y) |
                      (compute_idx(c_hi.x, c_hi.y) << 16);
        }
    }

    float vlo[PAIRS_PER_THREAD];
    float vhi[PAIRS_PER_THREAD];

    #pragma unroll
    for (int s = 0; s < NUM_STAGES; ++s) {
        if (tid == 0 && s + 2 < NUM_STAGES)
            bulk_copy_stage(sb + ((s + 2) % NUM_BUFS) * STAGE_BYTES,
                            plane + (size_t)(s + 2) * STAGE_PIX,
                            mb0 + ((s + 2) % NUM_BUFS) * 8);

        mbar_wait(mb0 + (s % NUM_BUFS) * 8, (unsigned)(s / NUM_BUFS));

        const float* cur = sbuf + (s % NUM_BUFS) * STAGE_PIX;
        const unsigned int us = (unsigned int)s;
        // Predicated LDS into registers; no stores in the stage loop.
        #pragma unroll
        for (int k = 0; k < PAIRS_PER_THREAD; ++k) {
            unsigned int pr = pair[k];
            unsigned int lo = pr & 0xFFFFu;
            unsigned int hi = pr >> 16;
            if ((lo >> 14) == us) vlo[k] = cur[lo & (STAGE_PIX - 1)];
            if ((hi >> 14) == us) vhi[k] = cur[hi & (STAGE_PIX - 1)];
        }
        __syncthreads();   // stage s fully read before buf (s%3) is rewritten
    }

    // Single dense store pass: every STG fully active and coalesced.
    #pragma unroll
    for (int k = 0; k < PAIRS_PER_THREAD; ++k) {
        int j = tid + (k << 10);
        ob[j]             = vlo[k];
        ob[j + GS_HALF_N] = vhi[k];
    }
}

extern "C" void kernel_launch(void* const* d_in, const int* in_sizes, int n_in,
                              void* d_out, int out_size) {
    const float* x      = (const float*)d_in[0];   // (8,128,256,256) f32
    const float* coords = (const float*)d_in[1];   // (8,32768,2) f32
    float* out          = (float*)d_out;           // (8,128,32768) f32

    static int smem_set = 0;
    if (!smem_set) {
        cudaFuncSetAttribute(gather_kernel,
                             cudaFuncAttributeMaxDynamicSharedMemorySize,
                             NUM_BUFS * STAGE_PIX * sizeof(float));
        smem_set = 1;
    }

    gather_kernel<<<GS_B * GS_C, K2_THREADS,
                    NUM_BUFS * STAGE_PIX * sizeof(float)>>>(x, coords, out);
}

// round 11
// speedup vs baseline: 1.2055x; 1.2055x over previous
#include <cuda_runtime.h>
#include <cstdint>

// nu_grid_sampler: out[b,c,n] = x[b,c,px,py], x:(8,128,256,256) f32,
// coords:(8,32768,2) f32, out:(8,128,32768) f32.
//
// R11 = R9 (best: 96.3us; TMA bulk stage copies, 4 x 16K-pixel stages,
// 3 x 64KB ring, lookahead 2, pair[16] in regs, predicated per-stage stores)
// + ONE change: index computation fused into the prologue (overlapped with
// the in-flight TMA for stages 0/1), eliminating the separate idx_kernel
// launch (~7.5us). R10's register-accumulation is reverted (it spilled:
// 48 array regs at the 64-reg/1024-thread cap).

#define GS_B 8
#define GS_C 128
#define GS_NX 256
#define GS_NY 256
#define GS_N 32768
#define GS_PIX (GS_NX * GS_NY)            // 65536
#define GS_HALF_N (GS_N / 2)              // 16384 pairs
#define STAGE_PIX 16384                    // 64KB per stage
#define STAGE_BYTES (STAGE_PIX * 4)
#define NUM_STAGES 4
#define NUM_BUFS 3
#define K2_THREADS 1024
#define PAIRS_PER_THREAD (GS_HALF_N / K2_THREADS)  // 16

__device__ __forceinline__ unsigned int compute_idx(float cy, float cx) {
    float pxf = fminf(fmaxf(cx * (float)(GS_NX - 1), 0.0f), (float)GS_NX);
    float pyf = fminf(fmaxf(cy * (float)(GS_NY - 1), 0.0f), (float)GS_NY);
    int idx = (int)pxf * GS_NY + (int)pyf;
    return (unsigned int)min(idx, GS_PIX - 1);       // take_along_axis clamp
}

__device__ __forceinline__ uint32_t smem_u32(const void* p) {
    uint32_t a;
    asm("{ .reg .u64 t; cvta.to.shared.u64 t, %1; cvt.u32.u64 %0, t; }"
        : "=r"(a) : "l"(p));
    return a;
}

// Single-thread bulk copy of one 64KB stage with transaction-tracked mbarrier.
__device__ __forceinline__ void bulk_copy_stage(uint32_t smem_dst, const float* gsrc,
                                                uint32_t mbar) {
    asm volatile("mbarrier.arrive.expect_tx.shared.b64 _, [%0], %1;"
                 :: "r"(mbar), "r"((unsigned)STAGE_BYTES) : "memory");
    asm volatile("cp.async.bulk.shared::cta.global.mbarrier::complete_tx::bytes "
                 "[%0], [%1], %2, [%3];"
                 :: "r"(smem_dst), "l"(gsrc), "r"((unsigned)STAGE_BYTES), "r"(mbar)
                 : "memory");
}

__device__ __forceinline__ void mbar_wait(uint32_t mbar, unsigned phase) {
    asm volatile(
        "{\n\t"
        ".reg .pred P;\n\t"
        "LAB_WAIT_%=:\n\t"
        "mbarrier.try_wait.parity.acquire.cta.shared::cta.b64 P, [%0], %1, 0x989680;\n\t"
        "@P bra.uni LAB_DONE_%=;\n\t"
        "bra.uni LAB_WAIT_%=;\n\t"
        "LAB_DONE_%=:\n\t"
        "}"
        :: "r"(mbar), "r"(phase) : "memory");
}

__global__ __launch_bounds__(K2_THREADS, 1)
void gather_kernel(const float* __restrict__ x,
                   const float* __restrict__ coords,
                   float* __restrict__ out) {
    extern __shared__ float sbuf[];                  // 3 * 16384 floats = 192KB
    __shared__ __align__(8) unsigned long long mbar_store[NUM_BUFS];
    const int tid = threadIdx.x;
    const int bc  = blockIdx.x;                      // b*128 + c
    const int b   = bc >> 7;

    const float* __restrict__ plane = x + ((size_t)bc << 16);
    float* __restrict__ ob          = out + ((size_t)bc << 15);

    const uint32_t sb  = smem_u32(sbuf);
    const uint32_t mb0 = smem_u32(mbar_store);

    if (tid == 0) {
        #pragma unroll
        for (int q = 0; q < NUM_BUFS; ++q)
            asm volatile("mbarrier.init.shared.b64 [%0], 1;"
                         :: "r"(mb0 + q * 8) : "memory");
    }
    __syncthreads();   // mbarrier init visible before any TMA

    // Issue stages 0 and 1 immediately; index math below hides their latency.
    if (tid == 0) {
        bulk_copy_stage(sb + 0 * STAGE_BYTES, plane + 0 * (size_t)STAGE_PIX, mb0 + 0);
        bulk_copy_stage(sb + 1 * STAGE_BYTES, plane + 1 * (size_t)STAGE_PIX, mb0 + 8);
    }

    // Fused index computation (coalesced float2 reads; coords set is L2-resident).
    unsigned int pair[PAIRS_PER_THREAD];
    {
        const float2* __restrict__ cb =
            reinterpret_cast<const float2*>(coords) + (size_t)b * GS_N + tid;
        #pragma unroll
        for (int k = 0; k < PAIRS_PER_THREAD; ++k) {
            float2 c_lo = cb[k << 10];
            float2 c_hi = cb[(k << 10) + GS_HALF_N];
            pair[k] = compute_idx(c_lo.x, c_lo.y) |
                      (compute_idx(c_hi.x, c_hi.y) << 16);
        }
    }

    #pragma unroll
    for (int s = 0; s < NUM_STAGES; ++s) {
        if (tid == 0 && s + 2 < NUM_STAGES)
            bulk_copy_stage(sb + ((s + 2) % NUM_BUFS) * STAGE_BYTES,
                            plane + (size_t)(s + 2) * STAGE_PIX,
                            mb0 + ((s + 2) % NUM_BUFS) * 8);

        mbar_wait(mb0 + (s % NUM_BUFS) * 8, (unsigned)(s / NUM_BUFS));

        const float* cur = sbuf + (s % NUM_BUFS) * STAGE_PIX;
        const unsigned int us = (unsigned int)s;
        // Predicated LDS gather + predicated coalesced stores (R9 proven loop).
        #pragma unroll
        for (int k = 0; k < PAIRS_PER_THREAD; ++k) {
            unsigned int pr = pair[k];
            unsigned int lo = pr & 0xFFFFu;
            unsigned int hi = pr >> 16;
            int j = tid + (k << 10);
            if ((lo >> 14) == us) ob[j]             = cur[lo & (STAGE_PIX - 1)];
            if ((hi >> 14) == us) ob[j + GS_HALF_N] = cur[hi & (STAGE_PIX - 1)];
        }
        __syncthreads();   // stage s fully read before buf (s%3) is rewritten
    }
}

extern "C" void kernel_launch(void* const* d_in, const int* in_sizes, int n_in,
                              void* d_out, int out_size) {
    const float* x      = (const float*)d_in[0];   // (8,128,256,256) f32
    const float* coords = (const float*)d_in[1];   // (8,32768,2) f32
    float* out          = (float*)d_out;           // (8,128,32768) f32

    static int smem_set = 0;
    if (!smem_set) {
        cudaFuncSetAttribute(gather_kernel,
                             cudaFuncAttributeMaxDynamicSharedMemorySize,
                             NUM_BUFS * STAGE_PIX * sizeof(float));
        smem_set = 1;
    }

    gather_kernel<<<GS_B * GS_C, K2_THREADS,
                    NUM_BUFS * STAGE_PIX * sizeof(float)>>>(x, coords, out);
}

// round 12
// speedup vs baseline: 1.3538x; 1.1230x over previous
#include <cuda_runtime.h>
#include <cstdint>

// nu_grid_sampler: out[b,c,n] = x[b,c,px,py], x:(8,128,256,256) f32,
// coords:(8,32768,2) f32, out:(8,128,32768) f32.
//
// R12 = R9 (best structure: idx_kernel + TMA bulk stage copies, 4 x 16K-pixel
// stages, 3 x 64KB ring, pair[16] in regs, predicated coalesced stores) with
// ALL in-loop block barriers removed. Rationale: R9's stage time (3.2us) is
// ~2x its issued work; the 2 x __syncthreads per stage couple 32 warps to the
// slowest (per-warp gather load is binomial -> barrier-max ~1.4x mean).
// With only 4 stages and 3 buffers, just buffer 0 is ever reused: TMA for
// stages 0..2 issues in the prologue; warps drift independently on per-buffer
// 'full' mbarriers; a 32-arrival 'done' mbarrier gates the single buffer-0
// reissue (stage 3), awaited only by warp 0.

#define GS_B 8
#define GS_C 128
#define GS_NX 256
#define GS_NY 256
#define GS_N 32768
#define GS_PIX (GS_NX * GS_NY)            // 65536
#define GS_HALF_N (GS_N / 2)              // 16384 pairs
#define STAGE_PIX 16384                    // 64KB per stage
#define STAGE_BYTES (STAGE_PIX * 4)
#define NUM_STAGES 4
#define NUM_BUFS 3
#define K2_THREADS 1024
#define PAIRS_PER_THREAD (GS_HALF_N / K2_THREADS)  // 16

// g_pack[b*16384 + j] = idx(n=j) | (idx(n=j+16384) << 16)
__device__ unsigned int g_pack[GS_B * GS_HALF_N];   // 512 KB scratch

__device__ __forceinline__ unsigned int compute_idx(float cy, float cx) {
    float pxf = fminf(fmaxf(cx * (float)(GS_NX - 1), 0.0f), (float)GS_NX);
    float pyf = fminf(fmaxf(cy * (float)(GS_NY - 1), 0.0f), (float)GS_NY);
    int idx = (int)pxf * GS_NY + (int)pyf;
    return (unsigned int)min(idx, GS_PIX - 1);       // take_along_axis clamp
}

__global__ __launch_bounds__(256)
void idx_kernel(const float* __restrict__ coords) {
    int j = blockIdx.x * blockDim.x + threadIdx.x;   // 0..16383
    int b = blockIdx.y;
    const float2* cb = reinterpret_cast<const float2*>(coords) + (size_t)b * GS_N;
    float2 c_lo = cb[j];
    float2 c_hi = cb[j + GS_HALF_N];
    g_pack[b * GS_HALF_N + j] =
        compute_idx(c_lo.x, c_lo.y) | (compute_idx(c_hi.x, c_hi.y) << 16);
}

__device__ __forceinline__ uint32_t smem_u32(const void* p) {
    uint32_t a;
    asm("{ .reg .u64 t; cvta.to.shared.u64 t, %1; cvt.u32.u64 %0, t; }"
        : "=r"(a) : "l"(p));
    return a;
}

__device__ __forceinline__ void bulk_copy_stage(uint32_t smem_dst, const float* gsrc,
                                                uint32_t mbar) {
    asm volatile("mbarrier.arrive.expect_tx.shared.b64 _, [%0], %1;"
                 :: "r"(mbar), "r"((unsigned)STAGE_BYTES) : "memory");
    asm volatile("cp.async.bulk.shared::cta.global.mbarrier::complete_tx::bytes "
                 "[%0], [%1], %2, [%3];"
                 :: "r"(smem_dst), "l"(gsrc), "r"((unsigned)STAGE_BYTES), "r"(mbar)
                 : "memory");
}

__device__ __forceinline__ void mbar_wait(uint32_t mbar, unsigned phase) {
    asm volatile(
        "{\n\t"
        ".reg .pred P;\n\t"
        "LAB_WAIT_%=:\n\t"
        "mbarrier.try_wait.parity.acquire.cta.shared::cta.b64 P, [%0], %1, 0x989680;\n\t"
        "@P bra.uni LAB_DONE_%=;\n\t"
        "bra.uni LAB_WAIT_%=;\n\t"
        "LAB_DONE_%=:\n\t"
        "}"
        :: "r"(mbar), "r"(phase) : "memory");
}

__global__ __launch_bounds__(K2_THREADS, 1)
void gather_kernel(const float* __restrict__ x, float* __restrict__ out) {
    extern __shared__ float sbuf[];                  // 3 * 16384 floats = 192KB
    __shared__ __align__(8) unsigned long long mbar_store[NUM_BUFS + 1]; // full[3], done
    const int tid = threadIdx.x;
    const int bc  = blockIdx.x;                      // b*128 + c
    const int b   = bc >> 7;

    const float* __restrict__ plane = x + ((size_t)bc << 16);
    float* __restrict__ ob          = out + ((size_t)bc << 15);

    const uint32_t sb   = smem_u32(sbuf);
    const uint32_t mb   = smem_u32(mbar_store);      // full[q] at mb+8q
    const uint32_t mdone = mb + NUM_BUFS * 8;

    if (tid == 0) {
        #pragma unroll
        for (int q = 0; q < NUM_BUFS; ++q)
            asm volatile("mbarrier.init.shared.b64 [%0], 1;"
                         :: "r"(mb + q * 8) : "memory");
        asm volatile("mbarrier.init.shared.b64 [%0], 32;"   // one arrive per warp
                     :: "r"(mdone) : "memory");
    }
    __syncthreads();   // the ONLY block barrier

    // Prologue: issue TMA for stages 0,1,2 (buffers 0,1,2).
    if (tid == 0) {
        bulk_copy_stage(sb + 0 * STAGE_BYTES, plane + 0 * (size_t)STAGE_PIX, mb + 0);
        bulk_copy_stage(sb + 1 * STAGE_BYTES, plane + 1 * (size_t)STAGE_PIX, mb + 8);
        bulk_copy_stage(sb + 2 * STAGE_BYTES, plane + 2 * (size_t)STAGE_PIX, mb + 16);
    }

    // Load this thread's 16 packed index pairs (overlaps TMA latency).
    unsigned int pair[PAIRS_PER_THREAD];
    const unsigned int* __restrict__ pk = g_pack + b * GS_HALF_N + tid;
    #pragma unroll
    for (int k = 0; k < PAIRS_PER_THREAD; ++k)
        pair[k] = pk[k << 10];

    // ---- Stage 0 (buffer 0, phase 0) ----
    mbar_wait(mb + 0, 0);
    {
        const float* cur = sbuf;
        #pragma unroll
        for (int k = 0; k < PAIRS_PER_THREAD; ++k) {
            unsigned int pr = pair[k];
            unsigned int lo = pr & 0xFFFFu;
            unsigned int hi = pr >> 16;
            int j = tid + (k << 10);
            if ((lo >> 14) == 0u) ob[j]             = cur[lo & (STAGE_PIX - 1)];
            if ((hi >> 14) == 0u) ob[j + GS_HALF_N] = cur[hi & (STAGE_PIX - 1)];
        }
    }
    // Every warp signals stage-0 completion (buffer 0 drained by this warp).
    if ((tid & 31) == 0)
        asm volatile("mbarrier.arrive.shared.b64 _, [%0];" :: "r"(mdone) : "memory");
    // Producer alone waits for all warps, then reissues buffer 0 for stage 3.
    if (tid == 0) {
        mbar_wait(mdone, 0);
        bulk_copy_stage(sb + 0 * STAGE_BYTES, plane + 3 * (size_t)STAGE_PIX, mb + 0);
    }

    // ---- Stage 1 (buffer 1, phase 0) ----
    mbar_wait(mb + 8, 0);
    {
        const float* cur = sbuf + 1 * STAGE_PIX;
        #pragma unroll
        for (int k = 0; k < PAIRS_PER_THREAD; ++k) {
            unsigned int pr = pair[k];
            unsigned int lo = pr & 0xFFFFu;
            unsigned int hi = pr >> 16;
            int j = tid + (k << 10);
            if ((lo >> 14) == 1u) ob[j]             = cur[lo & (STAGE_PIX - 1)];
            if ((hi >> 14) == 1u) ob[j + GS_HALF_N] = cur[hi & (STAGE_PIX - 1)];
        }
    }

    // ---- Stage 2 (buffer 2, phase 0) ----
    mbar_wait(mb + 16, 0);
    {
        const float* cur = sbuf + 2 * STAGE_PIX;
        #pragma unroll
        for (int k = 0; k < PAIRS_PER_THREAD; ++k) {
            unsigned int pr = pair[k];
            unsigned int lo = pr & 0xFFFFu;
            unsigned int hi = pr >> 16;
            int j = tid + (k << 10);
            if ((lo >> 14) == 2u) ob[j]             = cur[lo & (STAGE_PIX - 1)];
            if ((hi >> 14) == 2u) ob[j + GS_HALF_N] = cur[hi & (STAGE_PIX - 1)];
        }
    }

    // ---- Stage 3 (buffer 0, phase 1) ----
    mbar_wait(mb + 0, 1);
    {
        const float* cur = sbuf;
        #pragma unroll
        for (int k = 0; k < PAIRS_PER_THREAD; ++k) {
            unsigned int pr = pair[k];
            unsigned int lo = pr & 0xFFFFu;
            unsigned int hi = pr >> 16;
            int j = tid + (k << 10);
            if ((lo >> 14) == 3u) ob[j]             = cur[lo & (STAGE_PIX - 1)];
            if ((hi >> 14) == 3u) ob[j + GS_HALF_N] = cur[hi & (STAGE_PIX - 1)];
        }
    }
}

extern "C" void kernel_launch(void* const* d_in, const int* in_sizes, int n_in,
                              void* d_out, int out_size) {
    const float* x      = (const float*)d_in[0];   // (8,128,256,256) f32
    const float* coords = (const float*)d_in[1];   // (8,32768,2) f32
    float* out          = (float*)d_out;           // (8,128,32768) f32

    static int smem_set = 0;
    if (!smem_set) {
        cudaFuncSetAttribute(gather_kernel,
                             cudaFuncAttributeMaxDynamicSharedMemorySize,
                             NUM_BUFS * STAGE_PIX * sizeof(float));
        smem_set = 1;
    }

    idx_kernel<<<dim3(GS_HALF_N / 256, GS_B), 256>>>(coords);
    gather_kernel<<<GS_B * GS_C, K2_THREADS,
                    NUM_BUFS * STAGE_PIX * sizeof(float)>>>(x, out);
}